// round 10
// baseline (speedup 1.0000x reference)
#include <cuda_runtime.h>
#include <math.h>
#include <float.h>

#define BS    4096
#define LSEQ  200
#define VOCAB 100000
#define ESTR  66    // k_es EsmT64 u64 row stride
#define HS    68    // hisP float row stride

typedef unsigned long long u64;

// ---- packed fp32x2 helpers (Blackwell FFMA2 path) ----
__device__ __forceinline__ u64 pack2(float x, float y) {
    u64 r; asm("mov.b64 %0, {%1, %2};" : "=l"(r) : "f"(x), "f"(y)); return r;
}
__device__ __forceinline__ u64 pack_dup(float x) {
    u64 r; asm("mov.b64 %0, {%1, %1};" : "=l"(r) : "f"(x)); return r;
}
__device__ __forceinline__ void unpack2(u64 v, float& x, float& y) {
    asm("mov.b64 {%0, %1}, %2;" : "=f"(x), "=f"(y) : "l"(v));
}
__device__ __forceinline__ void ffma2(u64& d, u64 a, u64 b) {
    asm("fma.rn.f32x2 %0, %1, %2, %0;" : "+l"(d) : "l"(a), "l"(b));
}
__device__ __forceinline__ u64 fadd2(u64 a, u64 b) {
    u64 r; asm("add.rn.f32x2 %0, %1, %2;" : "=l"(r) : "l"(a), "l"(b)); return r;
}

// Scratch (allocation-free: device globals)
__device__ float g_ES[VOCAB * 64];            // 25.6 MB: E @ S, row 0 zeroed
__device__ float g_caps[BS * 4 * 64];         // 4 MB: routing output
__device__ float g_sink[32];

__global__ void k_shift() { g_sink[threadIdx.x] = 0.f; }

// ---------------------------------------------------------------------------
// Kernel 1: ES = E @ S. Row-pair packed FFMA2 (unchanged).
// ---------------------------------------------------------------------------
__global__ __launch_bounds__(256, 4) void k_es(const float* __restrict__ E,
                                               const float* __restrict__ S) {
    extern __shared__ float sm[];
    float* Ssm  = sm;                        // 64*64
    u64*   EsmT = (u64*)(sm + 4096);         // [64 e][66] u64 row-pairs
    const int tid = threadIdx.x;
    const int v0 = blockIdx.x * 128;

    for (int i = tid; i < 1024; i += 256)
        ((float4*)Ssm)[i] = ((const float4*)S)[i];
    for (int i = tid; i < 1024; i += 256) {
        int rp = i >> 4, e4 = i & 15;
        int vA = v0 + 2 * rp, vB = vA + 1;
        float4 a = make_float4(0.f, 0.f, 0.f, 0.f), bv = a;
        if (vA < VOCAB) a  = *(const float4*)&E[(size_t)vA * 64 + e4 * 4];
        if (vB < VOCAB) bv = *(const float4*)&E[(size_t)vB * 64 + e4 * 4];
        EsmT[(4 * e4 + 0) * ESTR + rp] = pack2(a.x, bv.x);
        EsmT[(4 * e4 + 1) * ESTR + rp] = pack2(a.y, bv.y);
        EsmT[(4 * e4 + 2) * ESTR + rp] = pack2(a.z, bv.z);
        EsmT[(4 * e4 + 3) * ESTR + rp] = pack2(a.w, bv.w);
    }
    __syncthreads();

    const int vg = tid >> 4;
    const int dg = tid & 15;
    u64 acc[4][4];
#pragma unroll
    for (int q = 0; q < 4; q++)
#pragma unroll
        for (int c = 0; c < 4; c++) acc[q][c] = 0ull;

#pragma unroll 4
    for (int e = 0; e < 64; e++) {
        float4 sv = *(float4*)&Ssm[e * 64 + dg * 4];
        u64 sd[4];
        sd[0] = pack_dup(sv.x); sd[1] = pack_dup(sv.y);
        sd[2] = pack_dup(sv.z); sd[3] = pack_dup(sv.w);
        ulonglong2 eA = *(ulonglong2*)&EsmT[e * ESTR + vg * 4];
        ulonglong2 eB = *(ulonglong2*)&EsmT[e * ESTR + vg * 4 + 2];
#pragma unroll
        for (int c = 0; c < 4; c++) {
            ffma2(acc[0][c], eA.x, sd[c]);
            ffma2(acc[1][c], eA.y, sd[c]);
            ffma2(acc[2][c], eB.x, sd[c]);
            ffma2(acc[3][c], eB.y, sd[c]);
        }
    }

#pragma unroll
    for (int q = 0; q < 4; q++) {
        int vA = v0 + vg * 8 + 2 * q, vB = vA + 1;
        float4 oa, ob;
        unpack2(acc[q][0], oa.x, ob.x);
        unpack2(acc[q][1], oa.y, ob.y);
        unpack2(acc[q][2], oa.z, ob.z);
        unpack2(acc[q][3], oa.w, ob.w);
        if (vA < VOCAB) {
            if (vA == 0) oa = make_float4(0.f, 0.f, 0.f, 0.f);
            *(float4*)&g_ES[(size_t)vA * 64 + dg * 4] = oa;
        }
        if (vB < VOCAB) {
            *(float4*)&g_ES[(size_t)vB * 64 + dg * 4] = ob;
        }
    }
}

// ---------------------------------------------------------------------------
// Kernel 2: routing. One CTA/batch, 512 threads, 2 CTAs/SM (32 warps).
// caps GEMM from REGISTER h (16 warps x <=13 l each, quarter-aligned chunks);
// smem h only for the B-update. Softmax rescale folded into reduce.
// ---------------------------------------------------------------------------
__global__ __launch_bounds__(512, 2) void k_route(const int* __restrict__ his,
                                                  const float* __restrict__ B0) {
    extern __shared__ u64 smu[];
    u64*   part2 = smu;                        // [16 ch][k*32+dp]  2048 u64 = 16KB
    u64*   WkT2  = part2 + 2048;               // unused slot kept for alignment
    u64*   capsP = part2 + 2048;               // [k][dp] pair-packed caps  128 u64
    float* hisP  = (float*)(capsP + 128);      // [200][68] floats
    float* Bk    = hisP + LSEQ * HS;           // [k][l] 800
    float* Bpart = Bk + 800;                   // [2][k][l] 1600
    float* WkF   = Bpart + 1600;               // [l][k] unnormalized exp 800
    float* msum  = WkF + 800;                  // 16 (w = q*4+k)
    float* ssum  = msum + 16;                  // 16
    int*   idx   = (int*)(ssum + 16);          // 200

    const int tid  = threadIdx.x;
    const int b    = blockIdx.x;
    const int lane = tid & 31;
    const int w    = tid >> 5;                 // 0..15
    const int qw   = w >> 2;                   // quarter 0..3
    const int sub  = w & 3;
    const int l0   = qw * 50 + ((sub < 2) ? sub * 13 : 26 + (sub - 2) * 12);
    const int llen = (sub < 2) ? 13 : 12;
    const float DROPV = -2147483648.0f;

    for (int l = tid; l < LSEQ; l += 512) idx[l] = his[b * LSEQ + l];
    for (int t = tid; t < 4 * LSEQ; t += 512) Bk[t] = B0[t];
    __syncthreads();

    // Gather: warp w loads its l-chunk; register copy + smem copy
    u64 h2[13];
#pragma unroll
    for (int i = 0; i < 13; i++) {
        if (i < llen) {
            const int l = l0 + i;
            int v = idx[l];
            u64 h = ((const u64*)g_ES)[(size_t)v * 32 + lane];
            h2[i] = h;
            float x, y; unpack2(h, x, y);
            *(float2*)&hisP[l * HS + 2 * lane] = make_float2(x, y);
        }
    }

    for (int it = 0; it < 3; it++) {
        __syncthreads();   // Bk/idx (it=0: gather) ready

        // ---- softmax partials: warp w handles k = sub? no: k = w&3, q = w>>2 ----
        {
            const int k = w & 3;
            const int base = (w >> 2) * 50;
            float m = -FLT_MAX;
#pragma unroll 2
            for (int j = lane; j < 50; j += 32) {
                int l = base + j;
                float v = (idx[l] != 0) ? Bk[k * LSEQ + l] : DROPV;
                m = fmaxf(m, v);
            }
#pragma unroll
            for (int o = 16; o > 0; o >>= 1) m = fmaxf(m, __shfl_xor_sync(0xffffffffu, m, o));
            float s = 0.f;
#pragma unroll 2
            for (int j = lane; j < 50; j += 32) {
                int l = base + j;
                float v = (idx[l] != 0) ? Bk[k * LSEQ + l] : DROPV;
                float e = __expf(v - m);
                WkF[l * 4 + k] = e;
                s += e;
            }
#pragma unroll
            for (int o = 16; o > 0; o >>= 1) s += __shfl_xor_sync(0xffffffffu, s, o);
            if (lane == 0) { msum[(w >> 2) * 4 + k] = m; ssum[(w >> 2) * 4 + k] = s; }
        }
        __syncthreads();

        // ---- caps partials from REGISTER h: warp w = chunk w ----
        {
            u64 a0 = 0ull, a1 = 0ull, a2 = 0ull, a3 = 0ull;
#pragma unroll
            for (int i = 0; i < 13; i++) {
                if (i < llen) {
                    const int l = l0 + i;
                    float4 wl = *(float4*)&WkF[l * 4];   // LDS.128 broadcast
                    ffma2(a0, h2[i], pack_dup(wl.x));
                    ffma2(a1, h2[i], pack_dup(wl.y));
                    ffma2(a2, h2[i], pack_dup(wl.z));
                    ffma2(a3, h2[i], pack_dup(wl.w));
                }
            }
            part2[w * 128 +  0 + lane] = a0;
            part2[w * 128 + 32 + lane] = a1;
            part2[w * 128 + 64 + lane] = a2;
            part2[w * 128 + 96 + lane] = a3;
        }
        __syncthreads();

        // ---- reduce per quarter, apply softmax-combine factors, squash ----
        if (tid < 128) {
            const int k  = tid >> 5;
            const int dp = tid & 31;
            u64 cq[4];
#pragma unroll
            for (int q = 0; q < 4; q++) {
                u64 c = part2[(q * 4 + 0) * 128 + k * 32 + dp];
#pragma unroll
                for (int s2 = 1; s2 < 4; s2++)
                    c = fadd2(c, part2[(q * 4 + s2) * 128 + k * 32 + dp]);
                cq[q] = c;
            }
            float mq[4], sq4[4];
#pragma unroll
            for (int q = 0; q < 4; q++) { mq[q] = msum[q * 4 + k]; sq4[q] = ssum[q * 4 + k]; }
            float M = fmaxf(fmaxf(mq[0], mq[1]), fmaxf(mq[2], mq[3]));
            float e0 = __expf(mq[0] - M), e1 = __expf(mq[1] - M);
            float e2 = __expf(mq[2] - M), e3 = __expf(mq[3] - M);
            float Sinv = 1.f / (e0 * sq4[0] + e1 * sq4[1] + e2 * sq4[2] + e3 * sq4[3]);
            float f0 = e0 * Sinv, f1 = e1 * Sinv, f2 = e2 * Sinv, f3 = e3 * Sinv;

            float cx, cy, x, y;
            unpack2(cq[0], x, y); cx = x * f0;          cy = y * f0;
            unpack2(cq[1], x, y); cx = fmaf(x, f1, cx); cy = fmaf(y, f1, cy);
            unpack2(cq[2], x, y); cx = fmaf(x, f2, cx); cy = fmaf(y, f2, cy);
            unpack2(cq[3], x, y); cx = fmaf(x, f3, cx); cy = fmaf(y, f3, cy);

            float sq = cx * cx + cy * cy;
#pragma unroll
            for (int o = 16; o > 0; o >>= 1) sq += __shfl_xor_sync(0xffffffffu, sq, o);
            float n2 = sq;
            float n  = sqrtf(n2);
            float scale = n2 / ((1.f + n2) * n + 1e-9f);
            cx *= scale; cy *= scale;
            if (it == 2) {
                *(float2*)&g_caps[b * 256 + k * 64 + 2 * dp] = make_float2(cx, cy);
            } else {
                capsP[k * 32 + dp] = pack2(cx, cy);
            }
        }
        if (it == 2) break;
        __syncthreads();

        // ---- B-update partials: 400 threads = (l, d-half) ----
        {
            const int half = tid >> 8;          // 0/1
            const int r    = tid & 255;
            const int l    = (r < LSEQ) ? r : (LSEQ - 1);
            const int dq0  = half * 8;
            u64 s0 = 0ull, s1 = 0ull, s2 = 0ull, s3 = 0ull;
#pragma unroll
            for (int j = 0; j < 8; j++) {
                const int dq = dq0 + j;
                ulonglong2 h  = *(ulonglong2*)&hisP[l * HS + dq * 4];
                ulonglong2 c0 = *(ulonglong2*)&capsP[0 * 32 + 2 * dq];
                ulonglong2 c1 = *(ulonglong2*)&capsP[1 * 32 + 2 * dq];
                ulonglong2 c2 = *(ulonglong2*)&capsP[2 * 32 + 2 * dq];
                ulonglong2 c3 = *(ulonglong2*)&capsP[3 * 32 + 2 * dq];
                ffma2(s0, h.x, c0.x); ffma2(s0, h.y, c0.y);
                ffma2(s1, h.x, c1.x); ffma2(s1, h.y, c1.y);
                ffma2(s2, h.x, c2.x); ffma2(s2, h.y, c2.y);
                ffma2(s3, h.x, c3.x); ffma2(s3, h.y, c3.y);
            }
            if (r < LSEQ) {
                float x, y;
                unpack2(s0, x, y); Bpart[half * 800 + 0 * LSEQ + l] = x + y;
                unpack2(s1, x, y); Bpart[half * 800 + 1 * LSEQ + l] = x + y;
                unpack2(s2, x, y); Bpart[half * 800 + 2 * LSEQ + l] = x + y;
                unpack2(s3, x, y); Bpart[half * 800 + 3 * LSEQ + l] = x + y;
            }
        }
        __syncthreads();

        // ---- combine halves into Bk ----
        if (tid < LSEQ) {
#pragma unroll
            for (int k = 0; k < 4; k++)
                Bk[k * LSEQ + tid] += Bpart[k * LSEQ + tid] + Bpart[800 + k * LSEQ + tid];
        }
    }
}

// ---------------------------------------------------------------------------
// Kernel 3: batched MLP. 512 CTAs x 32 rows, f-chunked 4x64 (unchanged).
// ---------------------------------------------------------------------------
__global__ __launch_bounds__(256, 4) void k_mlp(const float* __restrict__ W1,
                                                const float* __restrict__ b1,
                                                const float* __restrict__ W2,
                                                const float* __restrict__ b2,
                                                float* __restrict__ out) {
    extern __shared__ float sm[];
    float* W1c = sm;                 // 64*64
    float* W2c = W1c + 4096;         // 64*64
    float* cs  = W2c + 4096;         // 32*65
    float* hs  = cs + 32 * 65;       // 32*68
    float* b1s = hs + 32 * 68;       // 256
    float* b2s = b1s + 256;          // 64
    const int tid  = threadIdx.x;
    const int row0 = blockIdx.x * 32;

    for (int i = tid; i < 2048; i += 256) {
        int r = i >> 6, e = i & 63;
        cs[r * 65 + e] = g_caps[row0 * 64 + i];
    }
    if (tid < 256) b1s[tid] = b1[tid];
    if (tid < 64)  b2s[tid] = b2[tid];

    const int rq = tid >> 4;
    const int dq = tid & 15;
    u64 acc2[2][2];
    acc2[0][0] = acc2[0][1] = acc2[1][0] = acc2[1][1] = 0ull;

    for (int ch = 0; ch < 4; ch++) {
        const int f0 = ch * 64;
        __syncthreads();
        for (int i4 = tid; i4 < 1024; i4 += 256) {
            int e = i4 >> 4, j4 = i4 & 15;
            ((float4*)W1c)[i4] = *(const float4*)&W1[e * 256 + f0 + j4 * 4];
        }
        for (int i4 = tid; i4 < 1024; i4 += 256)
            ((float4*)W2c)[i4] = ((const float4*)&W2[f0 * 64])[i4];
        __syncthreads();

        {
            u64 acc1[2][2];
            acc1[0][0] = acc1[0][1] = acc1[1][0] = acc1[1][1] = 0ull;
#pragma unroll 4
            for (int e = 0; e < 64; e++) {
                u64 cd0 = pack_dup(cs[(rq * 2 + 0) * 65 + e]);
                u64 cd1 = pack_dup(cs[(rq * 2 + 1) * 65 + e]);
                ulonglong2 wv = *(ulonglong2*)&W1c[e * 64 + dq * 4];
                ffma2(acc1[0][0], cd0, wv.x); ffma2(acc1[0][1], cd0, wv.y);
                ffma2(acc1[1][0], cd1, wv.x); ffma2(acc1[1][1], cd1, wv.y);
            }
            float4 bb = *(float4*)&b1s[f0 + dq * 4];
#pragma unroll
            for (int i = 0; i < 2; i++) {
                float4 h; float x, y;
                unpack2(acc1[i][0], x, y); h.x = fmaxf(x + bb.x, 0.f); h.y = fmaxf(y + bb.y, 0.f);
                unpack2(acc1[i][1], x, y); h.z = fmaxf(x + bb.z, 0.f); h.w = fmaxf(y + bb.w, 0.f);
                *(float4*)&hs[(rq * 2 + i) * 68 + dq * 4] = h;
            }
        }
        __syncthreads();

#pragma unroll 4
        for (int f = 0; f < 64; f++) {
            u64 hd0 = pack_dup(hs[(rq * 2 + 0) * 68 + f]);
            u64 hd1 = pack_dup(hs[(rq * 2 + 1) * 68 + f]);
            ulonglong2 wv = *(ulonglong2*)&W2c[f * 64 + dq * 4];
            ffma2(acc2[0][0], hd0, wv.x); ffma2(acc2[0][1], hd0, wv.y);
            ffma2(acc2[1][0], hd1, wv.x); ffma2(acc2[1][1], hd1, wv.y);
        }
    }

    float4 bb = *(float4*)&b2s[dq * 4];
#pragma unroll
    for (int i = 0; i < 2; i++) {
        float4 o; float x, y;
        unpack2(acc2[i][0], x, y); o.x = x + bb.x; o.y = y + bb.y;
        unpack2(acc2[i][1], x, y); o.z = x + bb.z; o.w = y + bb.w;
        *(float4*)&out[(size_t)(row0 + rq * 2 + i) * 64 + dq * 4] = o;
    }
}

// ---------------------------------------------------------------------------
static const int SMEM1 = 4096 * 4 + 64 * ESTR * 8;                              // 50,176 B
static const int SMEM2 = (2048 + 128) * 8 + (LSEQ * HS + 800 + 1600 + 800 + 32) * 4 + LSEQ * 4; // ~85.5 KB
static const int SMEM3 = (4096 + 4096 + 32 * 65 + 32 * 68 + 256 + 64) * 4;      // 51,072 B

extern "C" void kernel_launch(void* const* d_in, const int* in_sizes, int n_in,
                              void* d_out, int out_size) {
    const int*   his = (const int*)  d_in[0];
    const float* E   = (const float*)d_in[1];
    const float* S   = (const float*)d_in[2];
    const float* B0  = (const float*)d_in[3];
    const float* W1  = (const float*)d_in[4];
    const float* b1  = (const float*)d_in[5];
    const float* W2  = (const float*)d_in[6];
    const float* b2  = (const float*)d_in[7];
    float* out = (float*)d_out;

    cudaFuncSetAttribute(k_es,    cudaFuncAttributeMaxDynamicSharedMemorySize, SMEM1);
    cudaFuncSetAttribute(k_route, cudaFuncAttributeMaxDynamicSharedMemorySize, SMEM2);
    cudaFuncSetAttribute(k_mlp,   cudaFuncAttributeMaxDynamicSharedMemorySize, SMEM3);

    k_shift<<<1, 32>>>();   // keep ncu's fixed window (4th launch) on k_route
    k_shift<<<1, 32>>>();
    k_es<<<(VOCAB + 127) / 128, 256, SMEM1>>>(E, S);
    k_route<<<BS, 512, SMEM2>>>(his, B0);
    k_mlp<<<(BS * 4) / 32, 256, SMEM3>>>(W1, b1, W2, b2, out);
}

// round 11
// speedup vs baseline: 1.0871x; 1.0871x over previous
#include <cuda_runtime.h>
#include <math.h>
#include <float.h>

#define BS    4096
#define LSEQ  200
#define VOCAB 100000
#define ESTR  66    // k_es EsmT64 u64 row stride
#define HS    68    // hisP float row stride

typedef unsigned long long u64;

// ---- packed fp32x2 helpers (Blackwell FFMA2 path) ----
__device__ __forceinline__ u64 pack2(float x, float y) {
    u64 r; asm("mov.b64 %0, {%1, %2};" : "=l"(r) : "f"(x), "f"(y)); return r;
}
__device__ __forceinline__ u64 pack_dup(float x) {
    u64 r; asm("mov.b64 %0, {%1, %1};" : "=l"(r) : "f"(x)); return r;
}
__device__ __forceinline__ void unpack2(u64 v, float& x, float& y) {
    asm("mov.b64 {%0, %1}, %2;" : "=f"(x), "=f"(y) : "l"(v));
}
__device__ __forceinline__ void ffma2(u64& d, u64 a, u64 b) {
    asm("fma.rn.f32x2 %0, %1, %2, %0;" : "+l"(d) : "l"(a), "l"(b));
}
__device__ __forceinline__ u64 fadd2(u64 a, u64 b) {
    u64 r; asm("add.rn.f32x2 %0, %1, %2;" : "=l"(r) : "l"(a), "l"(b)); return r;
}

// Scratch (allocation-free: device globals)
__device__ float g_ES[VOCAB * 64];            // 25.6 MB: E @ S, row 0 zeroed
__device__ float g_caps[BS * 4 * 64];         // 4 MB: routing output
__device__ float g_sink[32];

__global__ void k_shift() { g_sink[threadIdx.x] = 0.f; }

// ---------------------------------------------------------------------------
// Kernel 1: ES = E @ S. Row-pair packed FFMA2 (unchanged).
// ---------------------------------------------------------------------------
__global__ __launch_bounds__(256, 4) void k_es(const float* __restrict__ E,
                                               const float* __restrict__ S) {
    extern __shared__ float sm[];
    float* Ssm  = sm;                        // 64*64
    u64*   EsmT = (u64*)(sm + 4096);         // [64 e][66] u64 row-pairs
    const int tid = threadIdx.x;
    const int v0 = blockIdx.x * 128;

    for (int i = tid; i < 1024; i += 256)
        ((float4*)Ssm)[i] = ((const float4*)S)[i];
    for (int i = tid; i < 1024; i += 256) {
        int rp = i >> 4, e4 = i & 15;
        int vA = v0 + 2 * rp, vB = vA + 1;
        float4 a = make_float4(0.f, 0.f, 0.f, 0.f), bv = a;
        if (vA < VOCAB) a  = *(const float4*)&E[(size_t)vA * 64 + e4 * 4];
        if (vB < VOCAB) bv = *(const float4*)&E[(size_t)vB * 64 + e4 * 4];
        EsmT[(4 * e4 + 0) * ESTR + rp] = pack2(a.x, bv.x);
        EsmT[(4 * e4 + 1) * ESTR + rp] = pack2(a.y, bv.y);
        EsmT[(4 * e4 + 2) * ESTR + rp] = pack2(a.z, bv.z);
        EsmT[(4 * e4 + 3) * ESTR + rp] = pack2(a.w, bv.w);
    }
    __syncthreads();

    const int vg = tid >> 4;
    const int dg = tid & 15;
    u64 acc[4][4];
#pragma unroll
    for (int q = 0; q < 4; q++)
#pragma unroll
        for (int c = 0; c < 4; c++) acc[q][c] = 0ull;

#pragma unroll 4
    for (int e = 0; e < 64; e++) {
        float4 sv = *(float4*)&Ssm[e * 64 + dg * 4];
        u64 sd[4];
        sd[0] = pack_dup(sv.x); sd[1] = pack_dup(sv.y);
        sd[2] = pack_dup(sv.z); sd[3] = pack_dup(sv.w);
        ulonglong2 eA = *(ulonglong2*)&EsmT[e * ESTR + vg * 4];
        ulonglong2 eB = *(ulonglong2*)&EsmT[e * ESTR + vg * 4 + 2];
#pragma unroll
        for (int c = 0; c < 4; c++) {
            ffma2(acc[0][c], eA.x, sd[c]);
            ffma2(acc[1][c], eA.y, sd[c]);
            ffma2(acc[2][c], eB.x, sd[c]);
            ffma2(acc[3][c], eB.y, sd[c]);
        }
    }

#pragma unroll
    for (int q = 0; q < 4; q++) {
        int vA = v0 + vg * 8 + 2 * q, vB = vA + 1;
        float4 oa, ob;
        unpack2(acc[q][0], oa.x, ob.x);
        unpack2(acc[q][1], oa.y, ob.y);
        unpack2(acc[q][2], oa.z, ob.z);
        unpack2(acc[q][3], oa.w, ob.w);
        if (vA < VOCAB) {
            if (vA == 0) oa = make_float4(0.f, 0.f, 0.f, 0.f);
            *(float4*)&g_ES[(size_t)vA * 64 + dg * 4] = oa;
        }
        if (vB < VOCAB) {
            *(float4*)&g_ES[(size_t)vB * 64 + dg * 4] = ob;
        }
    }
}

// ---------------------------------------------------------------------------
// Kernel 2: routing. One CTA/batch, 256 threads, 3 CTAs/SM.
// Caps phase uses ALL 8 warps: warp = l-chunk (25 l), lane = d-pair.
// Per j: 1 LDS.64 h (conflict-free) + 1 float4 W broadcast + ALU dup.
// B-update / reduce / softmax structure identical to the R9 champion.
// ---------------------------------------------------------------------------
__global__ __launch_bounds__(256, 3) void k_route(const int* __restrict__ his,
                                                  const float* __restrict__ B0) {
    extern __shared__ u64 smu[];
    u64*   part2 = smu;                        // [8 lc][k*32+dp]  1024 u64
    u64*   capsP = part2 + 1024;               // [k][dp] pair-packed caps  128 u64
    float* hisP  = (float*)(capsP + 128);      // [200][68] floats
    float* Bk    = hisP + LSEQ * HS;           // [k][l] 800
    float* WkF   = Bk + 800;                   // [l][4k] plain exp floats  800+pad
    float* msum  = WkF + 816;                  // 8
    float* ssum  = msum + 8;                   // 8
    int*   idx   = (int*)(ssum + 8);           // 200

    const int tid  = threadIdx.x;
    const int b    = blockIdx.x;
    const int lane = tid & 31;
    const int w    = tid >> 5;
    const float DROPV = -2147483648.0f;

    for (int l = tid; l < LSEQ; l += 256) idx[l] = his[b * LSEQ + l];
    for (int t = tid; t < 4 * LSEQ; t += 256) Bk[t] = B0[t];
    __syncthreads();

    // Gather hisP rows (coalesced LDG.128 from L2-resident g_ES)
    for (int t = tid; t < LSEQ * 16; t += 256) {
        int l = t >> 4, dq = t & 15;
        float4 v = *(const float4*)&g_ES[(size_t)idx[l] * 64 + dq * 4];
        *(float4*)&hisP[l * HS + dq * 4] = v;
    }
    __syncthreads();

    for (int it = 0; it < 3; it++) {
        // ---- split softmax: warp w handles k = w>>1, half = w&1 (100 l) ----
        {
            const int k = w >> 1;
            const int base = (w & 1) * 100;
            float m = -FLT_MAX;
            for (int j = lane; j < 100; j += 32) {
                int l = base + j;
                float v = (idx[l] != 0) ? Bk[k * LSEQ + l] : DROPV;
                m = fmaxf(m, v);
            }
#pragma unroll
            for (int o = 16; o > 0; o >>= 1) m = fmaxf(m, __shfl_xor_sync(0xffffffffu, m, o));
            float s = 0.f;
            for (int j = lane; j < 100; j += 32) {
                int l = base + j;
                float v = (idx[l] != 0) ? Bk[k * LSEQ + l] : DROPV;
                float e = __expf(v - m);
                WkF[l * 4 + k] = e;
                s += e;
            }
#pragma unroll
            for (int o = 16; o > 0; o >>= 1) s += __shfl_xor_sync(0xffffffffu, s, o);
            if (lane == 0) { msum[w] = m; ssum[w] = s; }
        }
        __syncthreads();

        // ---- caps partials: ALL 8 warps. warp = l-chunk (25 l), lane = dp ----
        {
            const int l0 = w * 25;
            u64 a0 = 0ull, a1 = 0ull, a2 = 0ull, a3 = 0ull;
#pragma unroll 5
            for (int j = 0; j < 25; j++) {
                const int l = l0 + j;
                u64 h2 = *(u64*)&hisP[l * HS + 2 * lane];   // LDS.64, conflict-free
                float4 wl = *(float4*)&WkF[l * 4];          // 1-wf broadcast
                ffma2(a0, h2, pack_dup(wl.x));
                ffma2(a1, h2, pack_dup(wl.y));
                ffma2(a2, h2, pack_dup(wl.z));
                ffma2(a3, h2, pack_dup(wl.w));
            }
            part2[w * 128 +  0 + lane] = a0;
            part2[w * 128 + 32 + lane] = a1;
            part2[w * 128 + 64 + lane] = a2;
            part2[w * 128 + 96 + lane] = a3;
        }
        __syncthreads();

        // ---- reduce (chunks 0-3 = half0, 4-7 = half1), combine, squash ----
        if (tid < 128) {
            const int k  = tid >> 5;
            const int dp = tid & 31;
            u64 cl = part2[k * 32 + dp];
#pragma unroll
            for (int lc = 1; lc < 4; lc++) cl = fadd2(cl, part2[lc * 128 + k * 32 + dp]);
            u64 ch = part2[4 * 128 + k * 32 + dp];
#pragma unroll
            for (int lc = 5; lc < 8; lc++) ch = fadd2(ch, part2[lc * 128 + k * 32 + dp]);

            float m0 = msum[2 * k], m1 = msum[2 * k + 1];
            float s0 = ssum[2 * k], s1 = ssum[2 * k + 1];
            float M  = fmaxf(m0, m1);
            float g0 = __expf(m0 - M), g1 = __expf(m1 - M);
            float Sinv = 1.f / (s0 * g0 + s1 * g1);
            float f0 = g0 * Sinv, f1 = g1 * Sinv;

            float lx, ly, hx, hy;
            unpack2(cl, lx, ly);
            unpack2(ch, hx, hy);
            float cx = lx * f0 + hx * f1;     // caps[k][2dp]
            float cy = ly * f0 + hy * f1;     // caps[k][2dp+1]

            float sq = cx * cx + cy * cy;
#pragma unroll
            for (int o = 16; o > 0; o >>= 1) sq += __shfl_xor_sync(0xffffffffu, sq, o);
            float n2 = sq;
            float n  = sqrtf(n2);
            float scale = n2 / ((1.f + n2) * n + 1e-9f);
            cx *= scale; cy *= scale;
            if (it == 2) {
                *(float2*)&g_caps[b * 256 + k * 64 + 2 * dp] = make_float2(cx, cy);
            } else {
                capsP[k * 32 + dp] = pack2(cx, cy);   // adjacent-pair packed
            }
        }
        if (it == 2) break;
        __syncthreads();

        // ---- B[k][l] += dot(caps[k], hisP[l]) : thread-per-l, quad-wide ----
        {
            const int l = (tid < LSEQ) ? tid : (LSEQ - 1);
            u64 s0 = 0ull, s1 = 0ull, s2 = 0ull, s3 = 0ull;
#pragma unroll 4
            for (int dq = 0; dq < 16; dq++) {
                ulonglong2 h  = *(ulonglong2*)&hisP[l * HS + dq * 4];
                ulonglong2 c0 = *(ulonglong2*)&capsP[0 * 32 + 2 * dq];  // bcast
                ulonglong2 c1 = *(ulonglong2*)&capsP[1 * 32 + 2 * dq];
                ulonglong2 c2 = *(ulonglong2*)&capsP[2 * 32 + 2 * dq];
                ulonglong2 c3 = *(ulonglong2*)&capsP[3 * 32 + 2 * dq];
                ffma2(s0, h.x, c0.x); ffma2(s0, h.y, c0.y);
                ffma2(s1, h.x, c1.x); ffma2(s1, h.y, c1.y);
                ffma2(s2, h.x, c2.x); ffma2(s2, h.y, c2.y);
                ffma2(s3, h.x, c3.x); ffma2(s3, h.y, c3.y);
            }
            if (tid < LSEQ) {
                float x, y;
                unpack2(s0, x, y); Bk[0 * LSEQ + l] += x + y;
                unpack2(s1, x, y); Bk[1 * LSEQ + l] += x + y;
                unpack2(s2, x, y); Bk[2 * LSEQ + l] += x + y;
                unpack2(s3, x, y); Bk[3 * LSEQ + l] += x + y;
            }
        }
        __syncthreads();
    }
}

// ---------------------------------------------------------------------------
// Kernel 3: batched MLP. 512 CTAs x 32 rows, f-chunked 4x64 (unchanged).
// ---------------------------------------------------------------------------
__global__ __launch_bounds__(256, 4) void k_mlp(const float* __restrict__ W1,
                                                const float* __restrict__ b1,
                                                const float* __restrict__ W2,
                                                const float* __restrict__ b2,
                                                float* __restrict__ out) {
    extern __shared__ float sm[];
    float* W1c = sm;                 // 64*64
    float* W2c = W1c + 4096;         // 64*64
    float* cs  = W2c + 4096;         // 32*65
    float* hs  = cs + 32 * 65;       // 32*68
    float* b1s = hs + 32 * 68;       // 256
    float* b2s = b1s + 256;          // 64
    const int tid  = threadIdx.x;
    const int row0 = blockIdx.x * 32;

    for (int i = tid; i < 2048; i += 256) {
        int r = i >> 6, e = i & 63;
        cs[r * 65 + e] = g_caps[row0 * 64 + i];
    }
    if (tid < 256) b1s[tid] = b1[tid];
    if (tid < 64)  b2s[tid] = b2[tid];

    const int rq = tid >> 4;
    const int dq = tid & 15;
    u64 acc2[2][2];
    acc2[0][0] = acc2[0][1] = acc2[1][0] = acc2[1][1] = 0ull;

    for (int ch = 0; ch < 4; ch++) {
        const int f0 = ch * 64;
        __syncthreads();
        for (int i4 = tid; i4 < 1024; i4 += 256) {
            int e = i4 >> 4, j4 = i4 & 15;
            ((float4*)W1c)[i4] = *(const float4*)&W1[e * 256 + f0 + j4 * 4];
        }
        for (int i4 = tid; i4 < 1024; i4 += 256)
            ((float4*)W2c)[i4] = ((const float4*)&W2[f0 * 64])[i4];
        __syncthreads();

        {
            u64 acc1[2][2];
            acc1[0][0] = acc1[0][1] = acc1[1][0] = acc1[1][1] = 0ull;
#pragma unroll 4
            for (int e = 0; e < 64; e++) {
                u64 cd0 = pack_dup(cs[(rq * 2 + 0) * 65 + e]);
                u64 cd1 = pack_dup(cs[(rq * 2 + 1) * 65 + e]);
                ulonglong2 wv = *(ulonglong2*)&W1c[e * 64 + dq * 4];
                ffma2(acc1[0][0], cd0, wv.x); ffma2(acc1[0][1], cd0, wv.y);
                ffma2(acc1[1][0], cd1, wv.x); ffma2(acc1[1][1], cd1, wv.y);
            }
            float4 bb = *(float4*)&b1s[f0 + dq * 4];
#pragma unroll
            for (int i = 0; i < 2; i++) {
                float4 h; float x, y;
                unpack2(acc1[i][0], x, y); h.x = fmaxf(x + bb.x, 0.f); h.y = fmaxf(y + bb.y, 0.f);
                unpack2(acc1[i][1], x, y); h.z = fmaxf(x + bb.z, 0.f); h.w = fmaxf(y + bb.w, 0.f);
                *(float4*)&hs[(rq * 2 + i) * 68 + dq * 4] = h;
            }
        }
        __syncthreads();

#pragma unroll 4
        for (int f = 0; f < 64; f++) {
            u64 hd0 = pack_dup(hs[(rq * 2 + 0) * 68 + f]);
            u64 hd1 = pack_dup(hs[(rq * 2 + 1) * 68 + f]);
            ulonglong2 wv = *(ulonglong2*)&W2c[f * 64 + dq * 4];
            ffma2(acc2[0][0], hd0, wv.x); ffma2(acc2[0][1], hd0, wv.y);
            ffma2(acc2[1][0], hd1, wv.x); ffma2(acc2[1][1], hd1, wv.y);
        }
    }

    float4 bb = *(float4*)&b2s[dq * 4];
#pragma unroll
    for (int i = 0; i < 2; i++) {
        float4 o; float x, y;
        unpack2(acc2[i][0], x, y); o.x = x + bb.x; o.y = y + bb.y;
        unpack2(acc2[i][1], x, y); o.z = x + bb.z; o.w = y + bb.w;
        *(float4*)&out[(size_t)(row0 + rq * 2 + i) * 64 + dq * 4] = o;
    }
}

// ---------------------------------------------------------------------------
static const int SMEM1 = 4096 * 4 + 64 * ESTR * 8;                              // 50,176 B
static const int SMEM2 = (1024 + 128) * 8 + (LSEQ * HS + 800 + 816 + 16) * 4 + LSEQ * 4; // 70,944 B
static const int SMEM3 = (4096 + 4096 + 32 * 65 + 32 * 68 + 256 + 64) * 4;      // 51,072 B

extern "C" void kernel_launch(void* const* d_in, const int* in_sizes, int n_in,
                              void* d_out, int out_size) {
    const int*   his = (const int*)  d_in[0];
    const float* E   = (const float*)d_in[1];
    const float* S   = (const float*)d_in[2];
    const float* B0  = (const float*)d_in[3];
    const float* W1  = (const float*)d_in[4];
    const float* b1  = (const float*)d_in[5];
    const float* W2  = (const float*)d_in[6];
    const float* b2  = (const float*)d_in[7];
    float* out = (float*)d_out;

    cudaFuncSetAttribute(k_es,    cudaFuncAttributeMaxDynamicSharedMemorySize, SMEM1);
    cudaFuncSetAttribute(k_route, cudaFuncAttributeMaxDynamicSharedMemorySize, SMEM2);
    cudaFuncSetAttribute(k_mlp,   cudaFuncAttributeMaxDynamicSharedMemorySize, SMEM3);

    k_shift<<<1, 32>>>();   // keep ncu's fixed window (4th launch) on k_route
    k_shift<<<1, 32>>>();
    k_es<<<(VOCAB + 127) / 128, 256, SMEM1>>>(E, S);
    k_route<<<BS, 256, SMEM2>>>(his, B0);
    k_mlp<<<(BS * 4) / 32, 256, SMEM3>>>(W1, b1, W2, b2, out);
}